// round 4
// baseline (speedup 1.0000x reference)
#include <cuda_runtime.h>
#include <cuda_bf16.h>
#include <cstdint>

// u_quant_weight_linear: per-out-channel uniform symmetric fake quantization.
// out[o,i] = clip(rint(w[o,i]/s), -qmax, qmax) * s
//   s = max(alh[o], 1e-5); b = rint(clip(|bit[o]|,1,6)); qmax = max(2^(b-1)-1, 1)
//
// R4: single-wave, perfectly balanced flat kernel.
// total float4 = 4096*2752 = 2^18 * 43.  Grid 1024 x 256 = 2^18 threads
// (one wave at occ>=7), each thread EXACTLY 43 items, no tail, no waves.
// Row index per item via constant division (2752 = 86*32 -> row is
// warp-uniform, so alh/bit loads are single-line broadcast L1 hits).

#define OUT_CH      4096
#define VEC_PER_ROW 2752u
#define TOTAL_VEC   (OUT_CH * VEC_PER_ROW)   // 11,272,192
#define NBLK        1024
#define NTHR        256
#define STRIDE      (NBLK * NTHR)            // 262,144
#define ITEMS       43

__device__ __forceinline__ void row_params(unsigned idx,
                                           const float* __restrict__ alh,
                                           const float* __restrict__ bit,
                                           float& s, float& qmax)
{
    const unsigned r = idx / VEC_PER_ROW;    // warp-uniform (2752 % 32 == 0)
    s = fmaxf(alh[r], 1e-5f);
    const float b = rintf(fminf(fmaxf(fabsf(bit[r]), 1.0f), 6.0f));
    qmax = fmaxf(exp2f(b - 1.0f) - 1.0f, 1.0f);
}

__device__ __forceinline__ float4 quant4(float4 v, float s, float qmax)
{
    const float qmin = -qmax;
    // True IEEE divide: rint decisions must match the reference exactly.
    v.x = fminf(fmaxf(rintf(v.x / s), qmin), qmax) * s;
    v.y = fminf(fmaxf(rintf(v.y / s), qmin), qmax) * s;
    v.z = fminf(fmaxf(rintf(v.z / s), qmin), qmax) * s;
    v.w = fminf(fmaxf(rintf(v.w / s), qmin), qmax) * s;
    return v;
}

__global__ __launch_bounds__(NTHR, 7)
void fake_quant_kernel(const float4* __restrict__ w,
                       const float*  __restrict__ alh,
                       const float*  __restrict__ bit,
                       float4* __restrict__ out)
{
    const unsigned gid = blockIdx.x * NTHR + threadIdx.x;

    // 21 batch-2 iterations (items 0..41), MLP 2 in-thread; full-chip
    // occupancy (2^18 threads resident) supplies the cross-warp MLP.
    #pragma unroll 1
    for (int i = 0; i < ITEMS - 1; i += 2) {
        const unsigned i0 = gid + (unsigned)i * STRIDE;
        const unsigned i1 = i0 + STRIDE;
        float4 v0 = __ldcs(&w[i0]);
        float4 v1 = __ldcs(&w[i1]);
        float s0, q0, s1, q1;
        row_params(i0, alh, bit, s0, q0);
        row_params(i1, alh, bit, s1, q1);
        __stcs(&out[i0], quant4(v0, s0, q0));
        __stcs(&out[i1], quant4(v1, s1, q1));
    }

    // Item 42 (ITEMS is odd) — unconditional, every thread.
    const unsigned iL = gid + (unsigned)(ITEMS - 1) * STRIDE;
    float4 vL = __ldcs(&w[iL]);
    float sL, qL;
    row_params(iL, alh, bit, sL, qL);
    __stcs(&out[iL], quant4(vL, sL, qL));
}

extern "C" void kernel_launch(void* const* d_in, const int* in_sizes, int n_in,
                              void* d_out, int out_size)
{
    const float4* w   = (const float4*)d_in[0];  // weight [4096, 11008]
    const float*  alh = (const float*)d_in[1];   // [4096, 1]
    const float*  bit = (const float*)d_in[2];   // [4096, 1]
    float4* out = (float4*)d_out;

    fake_quant_kernel<<<NBLK, NTHR>>>(w, alh, bit, out);
}

// round 5
// speedup vs baseline: 1.1704x; 1.1704x over previous
#include <cuda_runtime.h>
#include <cuda_bf16.h>
#include <cstdint>

// u_quant_weight_linear: per-out-channel uniform symmetric fake quantization.
// out[o,i] = clip(rint(w[o,i]/s), -qmax, qmax) * s
//   s = max(alh[o], 1e-5); b = rint(clip(|bit[o]|,1,6)); qmax = max(2^(b-1)-1,1)
//
// R5: tail-free batch-8 tiling. Total float4 = 4096*2752 = 11272192 = 5504*2048.
// Grid 5504 x 256 threads, each thread front-batches EXACTLY 8 float4
// (stride 256 within the block's 2048-vec chunk). Zero predicates/tail.
// __launch_bounds__(256,5) caps regs at 51 -> 62.5% occ; MLP_p1=8.
// Outstanding-load product = 8 x 0.625 = 5.0 (R2: 4.6, R3: 3.8, R4: 1.4;
// measured BW tracked this product).

#define VEC_PER_ROW 2752u
#define NTHR        256
#define BATCH       8
#define CHUNK       (NTHR * BATCH)           // 2048
#define NBLK        5504                      // 5504*2048 = 11272192 exactly

__device__ __forceinline__ void row_params(unsigned idx,
                                           const float* __restrict__ alh,
                                           const float* __restrict__ bit,
                                           float& s, float& qmax)
{
    const unsigned r = idx / VEC_PER_ROW;    // warp-uniform (2752 % 32 == 0)
    s = fmaxf(alh[r], 1e-5f);
    const float b = rintf(fminf(fmaxf(fabsf(bit[r]), 1.0f), 6.0f));
    qmax = fmaxf(exp2f(b - 1.0f) - 1.0f, 1.0f);
}

__device__ __forceinline__ float4 quant4(float4 v, float s, float qmax)
{
    const float qmin = -qmax;
    // True IEEE divide: rint decisions must match the reference exactly.
    v.x = fminf(fmaxf(rintf(v.x / s), qmin), qmax) * s;
    v.y = fminf(fmaxf(rintf(v.y / s), qmin), qmax) * s;
    v.z = fminf(fmaxf(rintf(v.z / s), qmin), qmax) * s;
    v.w = fminf(fmaxf(rintf(v.w / s), qmin), qmax) * s;
    return v;
}

__global__ __launch_bounds__(NTHR, 5)
void fake_quant_kernel(const float4* __restrict__ w,
                       const float*  __restrict__ alh,
                       const float*  __restrict__ bit,
                       float4* __restrict__ out)
{
    const unsigned base = blockIdx.x * CHUNK + threadIdx.x;

    // Front-batch all 8 loads: 8 independent LDG.128 in flight per thread.
    float4 v[BATCH];
    #pragma unroll
    for (int i = 0; i < BATCH; i++)
        v[i] = __ldcs(&w[base + i * NTHR]);

    #pragma unroll
    for (int i = 0; i < BATCH; i++) {
        const unsigned idx = base + i * NTHR;
        float s, qmax;
        row_params(idx, alh, bit, s, qmax);
        __stcs(&out[idx], quant4(v[i], s, qmax));
    }
}

extern "C" void kernel_launch(void* const* d_in, const int* in_sizes, int n_in,
                              void* d_out, int out_size)
{
    const float4* w   = (const float4*)d_in[0];  // weight [4096, 11008]
    const float*  alh = (const float*)d_in[1];   // [4096, 1]
    const float*  bit = (const float*)d_in[2];   // [4096, 1]
    float4* out = (float4*)d_out;

    fake_quant_kernel<<<NBLK, NTHR>>>(w, alh, bit, out);
}